// round 14
// baseline (speedup 1.0000x reference)
#include <cuda_runtime.h>
#include <cuda_fp16.h>
#include <cstdint>

#define B_    4
#define N1_   2048
#define N2_   8192
#define C1_   256
#define C2_   128
#define INCH  384
#define OUTCH 256
#define BK    32                     // k-halfs per stage
#define RSTR  40                     // smem row stride in halfs (80B, conflict-free)
#define STAGES 4
#define A_STG (128 * RSTR)           // halfs per A stage (128 rows)
#define B_STG (64 * RSTR)            // halfs per B stage (64 rows)
#define DYN_SMEM ((STAGES * (A_STG + B_STG)) * 2)   // 61440 bytes

// Scratch (__device__ globals per allocation-free rule)
__device__ __half g_X  [B_ * N2_ * INCH];    // fp16 concat input
__device__ __half g_Y1 [B_ * N2_ * OUTCH];   // fp16 layer-1 output
__device__ __half g_W1h[OUTCH * INCH];       // [n][k] fp16
__device__ __half g_W2h[OUTCH * OUTCH];      // [n][k] fp16

// ---------------------------------------------------------------------------
// Kernel 0: transpose W -> [n][k] fp16
// ---------------------------------------------------------------------------
__global__ void prep_weights(const float* __restrict__ W1,
                             const float* __restrict__ W2)
{
    const int t = blockIdx.x * 256 + threadIdx.x;
    for (int i = t; i < INCH * OUTCH; i += gridDim.x * 256) {
        int k = i / OUTCH, n = i % OUTCH;
        g_W1h[n * INCH + k] = __float2half_rn(W1[i]);
    }
    for (int i = t; i < OUTCH * OUTCH; i += gridDim.x * 256) {
        int k = i / OUTCH, n = i % OUTCH;
        g_W2h[n * OUTCH + k] = __float2half_rn(W2[i]);
    }
}

// ---------------------------------------------------------------------------
// Kernel 1: KNN (K=3) + interp + concat -> g_X (fp16).
// 4 queries per warp (8 lanes each). Per step the 8 lanes of a group read a
// CONTIGUOUS 128B block of points, identical across the 4 groups -> 1 smem
// crossbar slot/step (4x less LDS than warp-per-query). Per-lane exact top-2
// + exact rare repair; width-8 shuffle merge with index tie-break.
// ---------------------------------------------------------------------------
__global__ __launch_bounds__(512) void knn_interp_kernel(
    const float* __restrict__ xyz1, const float* __restrict__ xyz2,
    const float* __restrict__ pts1, const float* __restrict__ pts2)
{
    __shared__ float4 sp[N1_];
    const int b   = blockIdx.y;
    const int tid = threadIdx.x;

    const float* x1 = xyz1 + (size_t)b * N1_ * 3;
    for (int p = tid; p < N1_; p += 512) {
        float x = x1[3*p], y = x1[3*p+1], z = x1[3*p+2];
        sp[p] = make_float4(x, y, z, x*x + y*y + z*z);
    }
    __syncthreads();

    const int lane = tid & 31;
    const int grp  = lane >> 3;          // 0..3 (query within warp)
    const int sub  = lane & 7;           // 0..7 (lane within group)
    const int q    = blockIdx.x * 64 + (tid >> 5) * 4 + grp;
    const int row  = b * N2_ + q;

    const float qx = xyz2[row*3+0];
    const float qy = xyz2[row*3+1];
    const float qz = xyz2[row*3+2];
    const float q2 = qx*qx + qy*qy + qz*qz;
    const float ax = -2.f*qx, ay = -2.f*qy, az = -2.f*qz;

    // per-lane top-2 of d' = |p|^2 - 2 q.p over points {sub, 8+sub, 16+sub, ...}
    float t0 = 3.4e38f, t1 = 3.4e38f;
    int   i0 = -1,      i1 = -1;

    int idx = sub;
    #pragma unroll 8
    for (int s = 0; s < N1_ / 8; ++s) {
        float4 p = sp[idx];
        float d = fmaf(ax, p.x, fmaf(ay, p.y, fmaf(az, p.z, p.w)));
        bool p1 = d < t1;
        bool p0 = d < t0;
        float nt1 = p0 ? t0 : d;
        int   ni1 = p0 ? i0 : idx;
        t1 = p1 ? nt1 : t1;  i1 = p1 ? ni1 : i1;
        t0 = p0 ? d   : t0;  i0 = p0 ? idx : i0;
        idx += 8;
    }

    // merge top-3 within the 8-lane group (3 rounds of argmin over heads);
    // tie-break by INDEX (matches reference top_k earliest-index policy)
    int head = 0;
    bool win0 = false, win1 = false;
    float selD[3]; int selI[3];
    #pragma unroll
    for (int r = 0; r < 3; ++r) {
        float cd = (head == 0) ? t0 : (head == 1) ? t1 : 3.4e38f;
        int   ci = (head == 0) ? i0 : (head == 1) ? i1 : 0x7fffffff;
        float bD = cd; int bI = ci; int bS = sub;
        #pragma unroll
        for (int off = 4; off; off >>= 1) {
            float od = __shfl_xor_sync(0xffffffffu, bD, off, 8);
            int   oi = __shfl_xor_sync(0xffffffffu, bI, off, 8);
            int   os = __shfl_xor_sync(0xffffffffu, bS, off, 8);
            if (od < bD || (od == bD && oi < bI)) { bD = od; bI = oi; bS = os; }
        }
        selD[r] = bD; selI[r] = bI;
        if (sub == bS) {
            if (r == 0) win0 = true;
            if (r == 1) win1 = true;
            head++;
        }
    }

    // exact repair: if one lane supplied BOTH of the first two winners, its
    // untracked 3rd-best may beat the reported 3rd. Rescan that lane's point
    // set cooperatively across the group's 8 lanes (32 steps).
    const unsigned bal = __ballot_sync(0xffffffffu, win0 && win1);
    if (bal) {                               // warp-uniform entry
        const unsigned gb = (bal >> (lane & 24)) & 0xffu;
        const int subL = gb ? (__ffs((int)gb) - 1) : 0;
        const int i0L = __shfl_sync(0xffffffffu, i0, subL, 8);
        const int i1L = __shfl_sync(0xffffffffu, i1, subL, 8);
        float d3 = 3.4e38f; int i3 = 0x7fffffff;
        int pid = sub * 256 + subL;          // lane j scans s in [32j, 32j+32)
        #pragma unroll 4
        for (int s = 0; s < 32; ++s) {
            float4 p = sp[pid];
            float d = fmaf(ax, p.x, fmaf(ay, p.y, fmaf(az, p.z, p.w)));
            bool ok = (pid != i0L) && (pid != i1L);
            if (ok && (d < d3 || (d == d3 && pid < i3))) { d3 = d; i3 = pid; }
            pid += 8;
        }
        #pragma unroll
        for (int off = 4; off; off >>= 1) {
            float od = __shfl_xor_sync(0xffffffffu, d3, off, 8);
            int   oi = __shfl_xor_sync(0xffffffffu, i3, off, 8);
            if (od < d3 || (od == d3 && oi < i3)) { d3 = od; i3 = oi; }
        }
        if (gb && (d3 < selD[2] || (d3 == selD[2] && i3 < selI[2]))) {
            selD[2] = d3; selI[2] = i3;
        }
    }

    float d0 = fmaxf(selD[0] + q2, 1e-10f);
    float d1 = fmaxf(selD[1] + q2, 1e-10f);
    float d2 = fmaxf(selD[2] + q2, 1e-10f);
    float w0 = 1.f / (d0 + 1e-8f);
    float w1 = 1.f / (d1 + 1e-8f);
    float w2 = 1.f / (d2 + 1e-8f);
    float inv = 1.f / (w0 + w1 + w2);
    w0 *= inv; w1 *= inv; w2 *= inv;

    const float* p0f = pts1 + (size_t)(b * N1_ + selI[0]) * C1_;
    const float* p1f = pts1 + (size_t)(b * N1_ + selI[1]) * C1_;
    const float* p2f = pts1 + (size_t)(b * N1_ + selI[2]) * C1_;
    __half* xr = g_X + (size_t)row * INCH;

    // interp: group covers 256 C1 channels; at fixed jj the 8 lanes touch a
    // contiguous 32-channel (128B) span
    #pragma unroll
    for (int jj = 0; jj < 8; ++jj) {
        const int c = jj * 32 + sub * 4;
        float4 a  = *(const float4*)(p0f + c);
        float4 bb = *(const float4*)(p1f + c);
        float4 cc = *(const float4*)(p2f + c);
        __half2 h0 = __floats2half2_rn(w0*a.x + w1*bb.x + w2*cc.x,
                                       w0*a.y + w1*bb.y + w2*cc.y);
        __half2 h1 = __floats2half2_rn(w0*a.z + w1*bb.z + w2*cc.z,
                                       w0*a.w + w1*bb.w + w2*cc.w);
        uint2 st; st.x = *(uint32_t*)&h0; st.y = *(uint32_t*)&h1;
        *(uint2*)(xr + c) = st;
    }
    {
        const float* pq = pts2 + (size_t)row * C2_;
        #pragma unroll
        for (int jj = 0; jj < 4; ++jj) {
            const int c = jj * 32 + sub * 4;
            float4 v = *(const float4*)(pq + c);
            __half2 h0 = __floats2half2_rn(v.x, v.y);
            __half2 h1 = __floats2half2_rn(v.z, v.w);
            uint2 st; st.x = *(uint32_t*)&h0; st.y = *(uint32_t*)&h1;
            *(uint2*)(xr + C1_ + c) = st;
        }
    }
}

// ---------------------------------------------------------------------------
// fp16 GEMM (frozen from R13, race-free): 128x64 tile, BK=32, 4-stage
// cp.async, wait_group 2 -> syncthreads -> read/mma -> issue -> commit.
// ldmatrix both operands, mma.m16n8k16, fused BN+ReLU. 8 warps, 3 CTAs/SM.
// ---------------------------------------------------------------------------
__device__ __forceinline__ void cp16b(void* dst, const void* src) {
    uint32_t d = (uint32_t)__cvta_generic_to_shared(dst);
    asm volatile("cp.async.cg.shared.global [%0], [%1], 16;\n" :: "r"(d), "l"(src));
}
__device__ __forceinline__ void cp_commit() {
    asm volatile("cp.async.commit_group;\n");
}
__device__ __forceinline__ void cp_wait2() {
    asm volatile("cp.async.wait_group 2;\n");
}
__device__ __forceinline__ void ldsm_x4(uint32_t& r0, uint32_t& r1,
                                        uint32_t& r2, uint32_t& r3, uint32_t addr) {
    asm volatile("ldmatrix.sync.aligned.m8n8.x4.shared.b16 {%0,%1,%2,%3}, [%4];\n"
                 : "=r"(r0), "=r"(r1), "=r"(r2), "=r"(r3) : "r"(addr));
}
__device__ __forceinline__ void mma_f16(float c[4], const uint32_t a[4],
                                        uint32_t b0, uint32_t b1) {
    asm volatile(
        "mma.sync.aligned.m16n8k16.row.col.f32.f16.f16.f32 "
        "{%0,%1,%2,%3}, {%4,%5,%6,%7}, {%8,%9}, {%0,%1,%2,%3};"
        : "+f"(c[0]), "+f"(c[1]), "+f"(c[2]), "+f"(c[3])
        : "r"(a[0]), "r"(a[1]), "r"(a[2]), "r"(a[3]), "r"(b0), "r"(b1));
}

template<int K, bool HALF_OUT>
__device__ __forceinline__ void gemm_body(
    const __half* __restrict__ A, const __half* __restrict__ Wp,
    const float* __restrict__ bias, const float* __restrict__ gamma,
    const float* __restrict__ beta, const float* __restrict__ rmean,
    const float* __restrict__ rvar, void* __restrict__ Cout)
{
    extern __shared__ __half sm[];
    __half* sA = sm;
    __half* sB = sm + STAGES * A_STG;

    const int tid  = threadIdx.x;
    const int lane = tid & 31;
    const int warp = tid >> 5;
    const int wm   = warp & 1;
    const int wn   = warp >> 1;
    const int m0   = blockIdx.y * 128;
    const int n0   = blockIdx.x * 64;
    const int g4   = lane >> 2;
    const int c4   = lane & 3;

    const int ar0 = tid >> 2,         ao0 = (tid & 3) * 8;
    const int ar1 = (tid + 256) >> 2, ao1 = ((tid + 256) & 3) * 8;
    const int br  = tid >> 2,         bo  = (tid & 3) * 8;

    const __half* Ag0 = A  + (size_t)(m0 + ar0) * K + ao0;
    const __half* Ag1 = A  + (size_t)(m0 + ar1) * K + ao1;
    const __half* Bg  = Wp + (size_t)(n0 + br) * K + bo;
    __half* sA0 = sA + ar0 * RSTR + ao0;
    __half* sA1 = sA + ar1 * RSTR + ao1;
    __half* sB0 = sB + br  * RSTR + bo;

    constexpr int NK = K / BK;

    float acc[4][2][4];
    #pragma unroll
    for (int i = 0; i < 4; ++i)
        #pragma unroll
        for (int j = 0; j < 2; ++j)
            #pragma unroll
            for (int r = 0; r < 4; ++r) acc[i][j][r] = 0.f;

    #pragma unroll
    for (int p = 0; p < STAGES - 1; ++p) {
        if (p < NK) {
            cp16b(sA0 + p * A_STG, Ag0 + p * BK);
            cp16b(sA1 + p * A_STG, Ag1 + p * BK);
            cp16b(sB0 + p * B_STG, Bg  + p * BK);
        }
        cp_commit();
    }

    const int a_row  = lane & 15;
    const int a_koff = (lane >= 16) ? 8 : 0;
    const int b_row  = ((lane >> 4) & 1) * 8 + (lane & 7);
    const int b_koff = ((lane >> 3) & 1) * 8;

    for (int kt = 0; kt < NK; ++kt) {
        cp_wait2();
        __syncthreads();

        const __half* stA = sA + (kt & (STAGES - 1)) * A_STG;
        const __half* stB = sB + (kt & (STAGES - 1)) * B_STG;

        #pragma unroll
        for (int kk = 0; kk < 2; ++kk) {
            uint32_t fa[4][4], fb[2][2];
            #pragma unroll
            for (int i = 0; i < 4; ++i) {
                const int r = wm * 64 + i * 16 + a_row;
                uint32_t addr = (uint32_t)__cvta_generic_to_shared(
                    stA + r * RSTR + kk * 16 + a_koff);
                ldsm_x4(fa[i][0], fa[i][1], fa[i][2], fa[i][3], addr);
            }
            {
                const int nr = wn * 16 + b_row;
                uint32_t addr = (uint32_t)__cvta_generic_to_shared(
                    stB + nr * RSTR + kk * 16 + b_koff);
                ldsm_x4(fb[0][0], fb[0][1], fb[1][0], fb[1][1], addr);
            }
            #pragma unroll
            for (int i = 0; i < 4; ++i)
                #pragma unroll
                for (int j = 0; j < 2; ++j)
                    mma_f16(acc[i][j], fa[i], fb[j][0], fb[j][1]);
        }

        const int nxtkt = kt + STAGES - 1;
        if (nxtkt < NK) {
            const int st = nxtkt & (STAGES - 1);
            cp16b(sA0 + st * A_STG, Ag0 + nxtkt * BK);
            cp16b(sA1 + st * A_STG, Ag1 + nxtkt * BK);
            cp16b(sB0 + st * B_STG, Bg  + nxtkt * BK);
        }
        cp_commit();
    }

    float sc[2][2], sh[2][2];
    #pragma unroll
    for (int j = 0; j < 2; ++j) {
        #pragma unroll
        for (int e = 0; e < 2; ++e) {
            const int col = n0 + wn * 16 + j * 8 + 2 * c4 + e;
            const float s = gamma[col] * rsqrtf(rvar[col] + 1e-5f);
            sc[j][e] = s;
            sh[j][e] = (bias[col] - rmean[col]) * s + beta[col];
        }
    }
    #pragma unroll
    for (int i = 0; i < 4; ++i) {
        const int r0 = m0 + wm * 64 + i * 16 + g4;
        #pragma unroll
        for (int j = 0; j < 2; ++j) {
            const int cb = n0 + wn * 16 + j * 8 + 2 * c4;
            float v0 = fmaxf(acc[i][j][0] * sc[j][0] + sh[j][0], 0.f);
            float v1 = fmaxf(acc[i][j][1] * sc[j][1] + sh[j][1], 0.f);
            float v2 = fmaxf(acc[i][j][2] * sc[j][0] + sh[j][0], 0.f);
            float v3 = fmaxf(acc[i][j][3] * sc[j][1] + sh[j][1], 0.f);
            if (HALF_OUT) {
                __half* C = (__half*)Cout;
                *(__half2*)(C + (size_t)r0 * OUTCH + cb)       = __floats2half2_rn(v0, v1);
                *(__half2*)(C + (size_t)(r0 + 8) * OUTCH + cb) = __floats2half2_rn(v2, v3);
            } else {
                float* C = (float*)Cout;
                *(float2*)(C + (size_t)r0 * OUTCH + cb)       = make_float2(v0, v1);
                *(float2*)(C + (size_t)(r0 + 8) * OUTCH + cb) = make_float2(v2, v3);
            }
        }
    }
}

__global__ __launch_bounds__(256, 3) void gemm1_f16(
    const float* __restrict__ bias, const float* __restrict__ gamma,
    const float* __restrict__ beta, const float* __restrict__ rmean,
    const float* __restrict__ rvar)
{
    gemm_body<INCH, true>(g_X, g_W1h, bias, gamma, beta, rmean, rvar, g_Y1);
}

__global__ __launch_bounds__(256, 3) void gemm2_f16(
    const float* __restrict__ bias, const float* __restrict__ gamma,
    const float* __restrict__ beta, const float* __restrict__ rmean,
    const float* __restrict__ rvar, float* __restrict__ C)
{
    gemm_body<OUTCH, false>(g_Y1, g_W2h, bias, gamma, beta, rmean, rvar, C);
}

// ---------------------------------------------------------------------------
extern "C" void kernel_launch(void* const* d_in, const int* in_sizes, int n_in,
                              void* d_out, int out_size)
{
    const float* xyz1 = (const float*)d_in[0];
    const float* xyz2 = (const float*)d_in[1];
    const float* pts1 = (const float*)d_in[2];
    const float* pts2 = (const float*)d_in[3];
    const float* W1   = (const float*)d_in[4];
    const float* b1   = (const float*)d_in[5];
    const float* g1   = (const float*)d_in[6];
    const float* be1  = (const float*)d_in[7];
    const float* rm1  = (const float*)d_in[8];
    const float* rv1  = (const float*)d_in[9];
    const float* W2   = (const float*)d_in[10];
    const float* b2   = (const float*)d_in[11];
    const float* g2   = (const float*)d_in[12];
    const float* be2  = (const float*)d_in[13];
    const float* rm2  = (const float*)d_in[14];
    const float* rv2  = (const float*)d_in[15];
    float* out = (float*)d_out;

    static bool attr_set = false;
    if (!attr_set) {
        cudaFuncSetAttribute(gemm1_f16,
            cudaFuncAttributeMaxDynamicSharedMemorySize, DYN_SMEM);
        cudaFuncSetAttribute(gemm2_f16,
            cudaFuncAttributeMaxDynamicSharedMemorySize, DYN_SMEM);
        attr_set = true;
    }

    prep_weights<<<64, 256>>>(W1, W2);
    knn_interp_kernel<<<dim3(N2_ / 64, B_), 512>>>(xyz1, xyz2, pts1, pts2);
    gemm1_f16<<<dim3(OUTCH / 64, (B_ * N2_) / 128), 256, DYN_SMEM>>>(b1, g1, be1, rm1, rv1);
    gemm2_f16<<<dim3(OUTCH / 64, (B_ * N2_) / 128), 256, DYN_SMEM>>>(b2, g2, be2, rm2, rv2, out);
}

// round 15
// speedup vs baseline: 1.1377x; 1.1377x over previous
#include <cuda_runtime.h>
#include <cuda_fp16.h>
#include <cstdint>

#define B_    4
#define N1_   2048
#define N2_   8192
#define C1_   256
#define C2_   128
#define INCH  384
#define OUTCH 256
#define BK    32                       // k-halfs per stage
#define RSTR  40                       // stage row stride (halfs) — bank-clean
#define RY    264                      // Y1 smem row stride (halfs) — bank-clean
#define STAGES 4
#define APART (128 * RSTR)             // A stage part  (halfs)
#define WPART (256 * RSTR)             // W stage part  (halfs)
#define STG   (APART + WPART)          // 15360 halfs per stage
#define Y1OFF (STAGES * STG)           // 61440 halfs
#define DSMEM ((Y1OFF + 128 * RY) * 2) // 190464 bytes

// Scratch (__device__ globals per allocation-free rule)
__device__ __half g_X  [B_ * N2_ * INCH];    // fp16 concat input
__device__ __half g_W1h[OUTCH * INCH];       // [n][k] fp16
__device__ __half g_W2h[OUTCH * OUTCH];      // [n][k] fp16

// ---------------------------------------------------------------------------
// Kernel 0: transpose W -> [n][k] fp16
// ---------------------------------------------------------------------------
__global__ void prep_weights(const float* __restrict__ W1,
                             const float* __restrict__ W2)
{
    const int t = blockIdx.x * 256 + threadIdx.x;
    for (int i = t; i < INCH * OUTCH; i += gridDim.x * 256) {
        int k = i / OUTCH, n = i % OUTCH;
        g_W1h[n * INCH + k] = __float2half_rn(W1[i]);
    }
    for (int i = t; i < OUTCH * OUTCH; i += gridDim.x * 256) {
        int k = i / OUTCH, n = i % OUTCH;
        g_W2h[n * OUTCH + k] = __float2half_rn(W2[i]);
    }
}

// ---------------------------------------------------------------------------
// Kernel 1 (R7-exact, measured-best): KNN (K=3) + interp + concat -> g_X
// ---------------------------------------------------------------------------
__global__ __launch_bounds__(512) void knn_interp_kernel(
    const float* __restrict__ xyz1, const float* __restrict__ xyz2,
    const float* __restrict__ pts1, const float* __restrict__ pts2)
{
    __shared__ float4 sp[N1_];
    const int b   = blockIdx.y;
    const int tid = threadIdx.x;

    const float* x1 = xyz1 + (size_t)b * N1_ * 3;
    for (int p = tid; p < N1_; p += 512) {
        float x = x1[3*p], y = x1[3*p+1], z = x1[3*p+2];
        sp[p] = make_float4(x, y, z, x*x + y*y + z*z);
    }
    __syncthreads();

    const int lane = tid & 31;
    const int q    = blockIdx.x * 16 + (tid >> 5);
    const int row  = b * N2_ + q;

    const float qx = xyz2[row*3+0];
    const float qy = xyz2[row*3+1];
    const float qz = xyz2[row*3+2];
    const float q2 = qx*qx + qy*qy + qz*qz;
    const float ax = -2.f*qx, ay = -2.f*qy, az = -2.f*qz;

    float t0 = 3.4e38f, t1 = 3.4e38f;
    int   i0 = -1,      i1 = -1;

    #pragma unroll 8
    for (int i = lane; i < N1_; i += 32) {
        float4 p = sp[i];
        float d = fmaf(ax, p.x, fmaf(ay, p.y, fmaf(az, p.z, p.w)));
        bool p1 = d < t1;
        bool p0 = d < t0;
        float nt1 = p0 ? t0 : d;
        int   ni1 = p0 ? i0 : i;
        t1 = p1 ? nt1 : t1;  i1 = p1 ? ni1 : i1;
        t0 = p0 ? d   : t0;  i0 = p0 ? i   : i0;
    }

    int head = 0;
    bool win0 = false, win1 = false;
    float selD[3]; int selI[3];
    #pragma unroll
    for (int r = 0; r < 3; ++r) {
        float cd  = (head == 0) ? t0 : (head == 1) ? t1 : 3.4e38f;
        int   ci  = (head == 0) ? i0 : (head == 1) ? i1 : 0;
        float bestD = cd; int bestLane = lane;
        #pragma unroll
        for (int off = 16; off; off >>= 1) {
            float od = __shfl_xor_sync(0xffffffffu, bestD, off);
            int   ol = __shfl_xor_sync(0xffffffffu, bestLane, off);
            if (od < bestD || (od == bestD && ol < bestLane)) { bestD = od; bestLane = ol; }
        }
        selD[r] = bestD;
        selI[r] = __shfl_sync(0xffffffffu, ci, bestLane);
        if (lane == bestLane) {
            if (r == 0) win0 = true;
            if (r == 1) win1 = true;
            head++;
        }
    }

    unsigned need = __ballot_sync(0xffffffffu, win0 && win1);
    if (need) {
        const int L = __ffs(need) - 1;
        float d3 = 3.4e38f; int i3 = 0x7fffffff;
        if (lane == L) {
            for (int i = lane; i < N1_; i += 32) {
                if (i == i0 || i == i1) continue;
                float4 p = sp[i];
                float d = fmaf(ax, p.x, fmaf(ay, p.y, fmaf(az, p.z, p.w)));
                if (d < d3 || (d == d3 && i < i3)) { d3 = d; i3 = i; }
            }
        }
        d3 = __shfl_sync(0xffffffffu, d3, L);
        i3 = __shfl_sync(0xffffffffu, i3, L);
        if (d3 < selD[2] || (d3 == selD[2] && i3 < selI[2])) {
            selD[2] = d3; selI[2] = i3;
        }
    }

    float d0 = fmaxf(selD[0] + q2, 1e-10f);
    float d1 = fmaxf(selD[1] + q2, 1e-10f);
    float d2 = fmaxf(selD[2] + q2, 1e-10f);
    float w0 = 1.f / (d0 + 1e-8f);
    float w1 = 1.f / (d1 + 1e-8f);
    float w2 = 1.f / (d2 + 1e-8f);
    float inv = 1.f / (w0 + w1 + w2);
    w0 *= inv; w1 *= inv; w2 *= inv;

    const float* p0f = pts1 + (size_t)(b * N1_ + selI[0]) * C1_;
    const float* p1f = pts1 + (size_t)(b * N1_ + selI[1]) * C1_;
    const float* p2f = pts1 + (size_t)(b * N1_ + selI[2]) * C1_;
    __half* xr = g_X + (size_t)row * INCH;

    const int c8 = lane * 8;
    {
        float4 a0 = *(const float4*)(p0f + c8);
        float4 b0 = *(const float4*)(p1f + c8);
        float4 c0 = *(const float4*)(p2f + c8);
        float4 a1 = *(const float4*)(p0f + c8 + 4);
        float4 b1 = *(const float4*)(p1f + c8 + 4);
        float4 c1 = *(const float4*)(p2f + c8 + 4);
        __half2 h[4];
        h[0] = __floats2half2_rn(w0*a0.x + w1*b0.x + w2*c0.x,
                                 w0*a0.y + w1*b0.y + w2*c0.y);
        h[1] = __floats2half2_rn(w0*a0.z + w1*b0.z + w2*c0.z,
                                 w0*a0.w + w1*b0.w + w2*c0.w);
        h[2] = __floats2half2_rn(w0*a1.x + w1*b1.x + w2*c1.x,
                                 w0*a1.y + w1*b1.y + w2*c1.y);
        h[3] = __floats2half2_rn(w0*a1.z + w1*b1.z + w2*c1.z,
                                 w0*a1.w + w1*b1.w + w2*c1.w);
        *(uint4*)(xr + c8) = *(uint4*)h;
    }
    {
        const float* pq = pts2 + (size_t)row * C2_;
        float4 v = *(const float4*)(pq + lane * 4);
        __half2 h[2];
        h[0] = __floats2half2_rn(v.x, v.y);
        h[1] = __floats2half2_rn(v.z, v.w);
        *(uint2*)(xr + C1_ + lane * 4) = *(uint2*)h;
    }
}

// ---------------------------------------------------------------------------
// Fused GEMM1+GEMM2: per CTA, 128 rows x ALL 256 cols.
//   Phase 1: Y1s[128x256] = relu(bn1(A[128x384] @ W1))   (Y1 stays in SMEM)
//   Phase 2: out[128x256] = relu(bn2(Y1s @ W2))          (A = SMEM ldmatrix)
// 512 threads = 16 warps (4m x 4n), warp 32x64. R13 race-free 4-stage
// cp.async pipeline for W (and phase-1 A) streaming.
// ---------------------------------------------------------------------------
__device__ __forceinline__ void cp16b(void* dst, const void* src) {
    uint32_t d = (uint32_t)__cvta_generic_to_shared(dst);
    asm volatile("cp.async.cg.shared.global [%0], [%1], 16;\n" :: "r"(d), "l"(src));
}
__device__ __forceinline__ void cp_commit() {
    asm volatile("cp.async.commit_group;\n");
}
__device__ __forceinline__ void cp_wait2() {
    asm volatile("cp.async.wait_group 2;\n");
}
__device__ __forceinline__ void cp_wait0() {
    asm volatile("cp.async.wait_group 0;\n");
}
__device__ __forceinline__ void ldsm_x4(uint32_t& r0, uint32_t& r1,
                                        uint32_t& r2, uint32_t& r3, uint32_t addr) {
    asm volatile("ldmatrix.sync.aligned.m8n8.x4.shared.b16 {%0,%1,%2,%3}, [%4];\n"
                 : "=r"(r0), "=r"(r1), "=r"(r2), "=r"(r3) : "r"(addr));
}
__device__ __forceinline__ void mma_f16(float c[4], const uint32_t a[4],
                                        uint32_t b0, uint32_t b1) {
    asm volatile(
        "mma.sync.aligned.m16n8k16.row.col.f32.f16.f16.f32 "
        "{%0,%1,%2,%3}, {%4,%5,%6,%7}, {%8,%9}, {%0,%1,%2,%3};"
        : "+f"(c[0]), "+f"(c[1]), "+f"(c[2]), "+f"(c[3])
        : "r"(a[0]), "r"(a[1]), "r"(a[2]), "r"(a[3]), "r"(b0), "r"(b1));
}

__global__ __launch_bounds__(512, 1) void gemm12_fused(
    const float* __restrict__ b1, const float* __restrict__ g1,
    const float* __restrict__ be1, const float* __restrict__ rm1,
    const float* __restrict__ rv1,
    const float* __restrict__ b2, const float* __restrict__ g2,
    const float* __restrict__ be2, const float* __restrict__ rm2,
    const float* __restrict__ rv2, float* __restrict__ out)
{
    extern __shared__ __align__(16) __half sm[];
    __half* y1s = sm + Y1OFF;

    const int tid  = threadIdx.x;
    const int lane = tid & 31;
    const int warp = tid >> 5;
    const int wm   = warp & 3;        // 4 m-groups (32 rows each)
    const int wn   = warp >> 2;       // 4 n-groups (64 cols each)
    const int m0   = blockIdx.x * 128;
    const int g4   = lane >> 2;
    const int c4   = lane & 3;

    // Loader mapping. A: 512 16B-units (128 rows x 4/row) -> thread t unit t.
    //                 W: 1024 units (256 rows x 4/row)    -> units 2t, 2t+1.
    const int a_r = tid >> 2, a_o = (tid & 3) * 8;
    const int w_r = tid >> 1, w_o = (tid & 1) * 16;   // two adjacent units

    const __half* Ag  = g_X   + (size_t)(m0 + a_r) * INCH + a_o;
    const __half* W1g = g_W1h + (size_t)w_r * INCH + w_o;
    const __half* W2g = g_W2h + (size_t)w_r * OUTCH + w_o;
    __half* sAme = sm + a_r * RSTR + a_o;
    __half* sWme = sm + APART + w_r * RSTR + w_o;

    const int a_row  = lane & 15;
    const int a_koff = (lane >= 16) ? 8 : 0;
    const int b_row  = ((lane >> 4) & 1) * 8 + (lane & 7);
    const int b_koff = ((lane >> 3) & 1) * 8;

    float acc[2][8][4];
    #pragma unroll
    for (int i = 0; i < 2; ++i)
        #pragma unroll
        for (int j = 0; j < 8; ++j)
            #pragma unroll
            for (int r = 0; r < 4; ++r) acc[i][j][r] = 0.f;

    // ================= Phase 1: A @ W1 =================
    constexpr int NK1 = INCH / BK;    // 12
    #pragma unroll
    for (int p = 0; p < STAGES - 1; ++p) {
        cp16b(sAme + p * STG, Ag + p * BK);
        cp16b(sWme + p * STG,     W1g + p * BK);
        cp16b(sWme + p * STG + 8, W1g + p * BK + 8);
        cp_commit();
    }

    for (int kt = 0; kt < NK1; ++kt) {
        cp_wait2();
        __syncthreads();

        const __half* stA = sm + (kt & (STAGES - 1)) * STG;
        const __half* stW = stA + APART;

        #pragma unroll
        for (int kk = 0; kk < 2; ++kk) {
            uint32_t fa[2][4], fb[8][2];
            #pragma unroll
            for (int i = 0; i < 2; ++i) {
                const int r = wm * 32 + i * 16 + a_row;
                uint32_t addr = (uint32_t)__cvta_generic_to_shared(
                    stA + r * RSTR + kk * 16 + a_koff);
                ldsm_x4(fa[i][0], fa[i][1], fa[i][2], fa[i][3], addr);
            }
            #pragma unroll
            for (int jh = 0; jh < 4; ++jh) {
                const int nr = wn * 64 + jh * 16 + b_row;
                uint32_t addr = (uint32_t)__cvta_generic_to_shared(
                    stW + nr * RSTR + kk * 16 + b_koff);
                ldsm_x4(fb[2*jh][0], fb[2*jh][1], fb[2*jh+1][0], fb[2*jh+1][1], addr);
            }
            #pragma unroll
            for (int i = 0; i < 2; ++i)
                #pragma unroll
                for (int j = 0; j < 8; ++j)
                    mma_f16(acc[i][j], fa[i], fb[j][0], fb[j][1]);
        }

        const int nxt = kt + STAGES - 1;
        if (nxt < NK1) {
            const int st = nxt & (STAGES - 1);
            cp16b(sAme + st * STG, Ag + nxt * BK);
            cp16b(sWme + st * STG,     W1g + nxt * BK);
            cp16b(sWme + st * STG + 8, W1g + nxt * BK + 8);
        }
        cp_commit();
    }

    // Phase-1 epilogue: bn1+relu -> half -> Y1 smem (bank-clean)
    #pragma unroll
    for (int j = 0; j < 8; ++j) {
        const int c0 = wn * 64 + j * 8 + 2 * c4;
        const float s0 = g1[c0]   * rsqrtf(rv1[c0]   + 1e-5f);
        const float s1 = g1[c0+1] * rsqrtf(rv1[c0+1] + 1e-5f);
        const float h0 = (b1[c0]   - rm1[c0])   * s0 + be1[c0];
        const float h1 = (b1[c0+1] - rm1[c0+1]) * s1 + be1[c0+1];
        #pragma unroll
        for (int i = 0; i < 2; ++i) {
            const int r0 = wm * 32 + i * 16 + g4;
            __half2 lo = __floats2half2_rn(fmaxf(acc[i][j][0]*s0 + h0, 0.f),
                                           fmaxf(acc[i][j][1]*s1 + h1, 0.f));
            __half2 hi = __floats2half2_rn(fmaxf(acc[i][j][2]*s0 + h0, 0.f),
                                           fmaxf(acc[i][j][3]*s1 + h1, 0.f));
            *(__half2*)(y1s + r0 * RY + c0)       = lo;
            *(__half2*)(y1s + (r0 + 8) * RY + c0) = hi;
        }
    }

    cp_wait0();          // drain all phase-1 groups before stage reuse
    __syncthreads();     // Y1 fully written & visible; stage buffers free

    // ================= Phase 2: Y1s @ W2 =================
    #pragma unroll
    for (int i = 0; i < 2; ++i)
        #pragma unroll
        for (int j = 0; j < 8; ++j)
            #pragma unroll
            for (int r = 0; r < 4; ++r) acc[i][j][r] = 0.f;

    constexpr int NK2 = OUTCH / BK;   // 8
    #pragma unroll
    for (int p = 0; p < STAGES - 1; ++p) {
        cp16b(sWme + p * STG,     W2g + p * BK);
        cp16b(sWme + p * STG + 8, W2g + p * BK + 8);
        cp_commit();
    }

    for (int kt = 0; kt < NK2; ++kt) {
        cp_wait2();
        __syncthreads();

        const __half* stW = sm + (kt & (STAGES - 1)) * STG + APART;

        #pragma unroll
        for (int kk = 0; kk < 2; ++kk) {
            uint32_t fa[2][4], fb[8][2];
            #pragma unroll
            for (int i = 0; i < 2; ++i) {
                const int r = wm * 32 + i * 16 + a_row;
                uint32_t addr = (uint32_t)__cvta_generic_to_shared(
                    y1s + r * RY + kt * 32 + kk * 16 + a_koff);
                ldsm_x4(fa[i][0], fa[i][1], fa[i][2], fa[i][3], addr);
            }
            #pragma unroll
            for (int jh = 0; jh < 4; ++jh) {
                const int nr = wn * 64 + jh * 16 + b_row;
                uint32_t addr = (uint32_t)__cvta_generic_to_shared(
                    stW + nr * RSTR + kk * 16 + b_koff);
                ldsm_x4(fb[2*jh][0], fb[2*jh][1], fb[2*jh+1][0], fb[2*jh+1][1], addr);
            }
            #pragma unroll
            for (int i = 0; i < 2; ++i)
                #pragma unroll
                for (int j = 0; j < 8; ++j)
                    mma_f16(acc[i][j], fa[i], fb[j][0], fb[j][1]);
        }

        const int nxt = kt + STAGES - 1;
        if (nxt < NK2) {
            const int st = nxt & (STAGES - 1);
            cp16b(sWme + st * STG,     W2g + nxt * BK);
            cp16b(sWme + st * STG + 8, W2g + nxt * BK + 8);
        }
        cp_commit();
    }

    // Phase-2 epilogue: bn2+relu -> fp32 gmem
    #pragma unroll
    for (int j = 0; j < 8; ++j) {
        const int c0 = wn * 64 + j * 8 + 2 * c4;
        const float s0 = g2[c0]   * rsqrtf(rv2[c0]   + 1e-5f);
        const float s1 = g2[c0+1] * rsqrtf(rv2[c0+1] + 1e-5f);
        const float h0 = (b2[c0]   - rm2[c0])   * s0 + be2[c0];
        const float h1 = (b2[c0+1] - rm2[c0+1]) * s1 + be2[c0+1];
        #pragma unroll
        for (int i = 0; i < 2; ++i) {
            const int r0 = m0 + wm * 32 + i * 16 + g4;
            float2 lo = make_float2(fmaxf(acc[i][j][0]*s0 + h0, 0.f),
                                    fmaxf(acc[i][j][1]*s1 + h1, 0.f));
            float2 hi = make_float2(fmaxf(acc[i][j][2]*s0 + h0, 0.f),
                                    fmaxf(acc[i][j][3]*s1 + h1, 0.f));
            *(float2*)(out + (size_t)r0 * OUTCH + c0)       = lo;
            *(float2*)(out + (size_t)(r0 + 8) * OUTCH + c0) = hi;
        }
    }
}

// ---------------------------------------------------------------------------
extern "C" void kernel_launch(void* const* d_in, const int* in_sizes, int n_in,
                              void* d_out, int out_size)
{
    const float* xyz1 = (const float*)d_in[0];
    const float* xyz2 = (const float*)d_in[1];
    const float* pts1 = (const float*)d_in[2];
    const float* pts2 = (const float*)d_in[3];
    const float* W1   = (const float*)d_in[4];
    const float* b1   = (const float*)d_in[5];
    const float* g1   = (const float*)d_in[6];
    const float* be1  = (const float*)d_in[7];
    const float* rm1  = (const float*)d_in[8];
    const float* rv1  = (const float*)d_in[9];
    const float* W2   = (const float*)d_in[10];
    const float* b2   = (const float*)d_in[11];
    const float* g2   = (const float*)d_in[12];
    const float* be2  = (const float*)d_in[13];
    const float* rm2  = (const float*)d_in[14];
    const float* rv2  = (const float*)d_in[15];
    float* out = (float*)d_out;

    static bool attr_set = false;
    if (!attr_set) {
        cudaFuncSetAttribute(gemm12_fused,
            cudaFuncAttributeMaxDynamicSharedMemorySize, DSMEM);
        attr_set = true;
    }

    prep_weights<<<64, 256>>>(W1, W2);
    knn_interp_kernel<<<dim3(N2_ / 16, B_), 512>>>(xyz1, xyz2, pts1, pts2);
    gemm12_fused<<<(B_ * N2_) / 128, 512, DSMEM>>>(
        b1, g1, be1, rm1, rv1, b2, g2, be2, rm2, rv2, out);
}

// round 16
// speedup vs baseline: 1.1936x; 1.0492x over previous
#include <cuda_runtime.h>
#include <cuda_fp16.h>
#include <cstdint>

#define B_    4
#define N1_   2048
#define N2_   8192
#define C1_   256
#define C2_   128
#define INCH  384
#define OUTCH 256
#define BK    32                       // k-halfs per stage
#define RSTR  40                       // stage row stride (halfs) — bank-clean
#define RY    264                      // Y1 smem row stride (halfs) — bank-clean
#define STAGES 4
#define APART (128 * RSTR)             // A stage part  (halfs)
#define WPART (256 * RSTR)             // W stage part  (halfs)
#define STG   (APART + WPART)          // 15360 halfs per stage
#define Y1OFF (STAGES * STG)           // 61440 halfs
#define DSMEM ((Y1OFF + 128 * RY) * 2) // 190464 bytes

// Scratch (__device__ globals per allocation-free rule)
__device__ __half g_X  [B_ * N2_ * INCH];    // fp16 concat input
__device__ __half g_W1h[OUTCH * INCH];       // [n][k] fp16
__device__ __half g_W2h[OUTCH * OUTCH];      // [n][k] fp16

// ---------------------------------------------------------------------------
// Kernel 0: tiled transpose W -> [n][k] fp16. 32x32 smem tiles, coalesced
// reads AND writes, bank-clean (stride 34 halfs). grid.z selects W1/W2.
// ---------------------------------------------------------------------------
__global__ void prep_weights(const float* __restrict__ W1,
                             const float* __restrict__ W2)
{
    __shared__ __half tile[32][34];
    const int z = blockIdx.z;
    const int K = z ? OUTCH : INCH;
    const float* src = z ? W2 : W1;          // [K][OUTCH] row-major
    __half* dst = z ? g_W2h : g_W1h;         // [OUTCH][K] row-major
    const int kb = blockIdx.x * 32;
    if (kb >= K) return;
    const int nb = blockIdx.y * 32;
    const int tx = threadIdx.x;              // 0..31
    const int ty = threadIdx.y;              // 0..7

    #pragma unroll
    for (int r = 0; r < 4; ++r) {
        const int k = kb + ty + r * 8;
        tile[ty + r * 8][tx] = __float2half_rn(src[(size_t)k * OUTCH + nb + tx]);
    }
    __syncthreads();
    #pragma unroll
    for (int r = 0; r < 4; ++r) {
        const int n = nb + ty + r * 8;
        dst[(size_t)n * K + kb + tx] = tile[tx][ty + r * 8];
    }
}

// ---------------------------------------------------------------------------
// Kernel 1 (R7-exact, measured-best): KNN (K=3) + interp + concat -> g_X
// ---------------------------------------------------------------------------
__global__ __launch_bounds__(512) void knn_interp_kernel(
    const float* __restrict__ xyz1, const float* __restrict__ xyz2,
    const float* __restrict__ pts1, const float* __restrict__ pts2)
{
    __shared__ float4 sp[N1_];
    const int b   = blockIdx.y;
    const int tid = threadIdx.x;

    const float* x1 = xyz1 + (size_t)b * N1_ * 3;
    for (int p = tid; p < N1_; p += 512) {
        float x = x1[3*p], y = x1[3*p+1], z = x1[3*p+2];
        sp[p] = make_float4(x, y, z, x*x + y*y + z*z);
    }
    __syncthreads();

    const int lane = tid & 31;
    const int q    = blockIdx.x * 16 + (tid >> 5);
    const int row  = b * N2_ + q;

    const float qx = xyz2[row*3+0];
    const float qy = xyz2[row*3+1];
    const float qz = xyz2[row*3+2];
    const float q2 = qx*qx + qy*qy + qz*qz;
    const float ax = -2.f*qx, ay = -2.f*qy, az = -2.f*qz;

    float t0 = 3.4e38f, t1 = 3.4e38f;
    int   i0 = -1,      i1 = -1;

    #pragma unroll 8
    for (int i = lane; i < N1_; i += 32) {
        float4 p = sp[i];
        float d = fmaf(ax, p.x, fmaf(ay, p.y, fmaf(az, p.z, p.w)));
        bool p1 = d < t1;
        bool p0 = d < t0;
        float nt1 = p0 ? t0 : d;
        int   ni1 = p0 ? i0 : i;
        t1 = p1 ? nt1 : t1;  i1 = p1 ? ni1 : i1;
        t0 = p0 ? d   : t0;  i0 = p0 ? i   : i0;
    }

    int head = 0;
    bool win0 = false, win1 = false;
    float selD[3]; int selI[3];
    #pragma unroll
    for (int r = 0; r < 3; ++r) {
        float cd  = (head == 0) ? t0 : (head == 1) ? t1 : 3.4e38f;
        int   ci  = (head == 0) ? i0 : (head == 1) ? i1 : 0;
        float bestD = cd; int bestLane = lane;
        #pragma unroll
        for (int off = 16; off; off >>= 1) {
            float od = __shfl_xor_sync(0xffffffffu, bestD, off);
            int   ol = __shfl_xor_sync(0xffffffffu, bestLane, off);
            if (od < bestD || (od == bestD && ol < bestLane)) { bestD = od; bestLane = ol; }
        }
        selD[r] = bestD;
        selI[r] = __shfl_sync(0xffffffffu, ci, bestLane);
        if (lane == bestLane) {
            if (r == 0) win0 = true;
            if (r == 1) win1 = true;
            head++;
        }
    }

    unsigned need = __ballot_sync(0xffffffffu, win0 && win1);
    if (need) {
        const int L = __ffs(need) - 1;
        float d3 = 3.4e38f; int i3 = 0x7fffffff;
        if (lane == L) {
            for (int i = lane; i < N1_; i += 32) {
                if (i == i0 || i == i1) continue;
                float4 p = sp[i];
                float d = fmaf(ax, p.x, fmaf(ay, p.y, fmaf(az, p.z, p.w)));
                if (d < d3 || (d == d3 && i < i3)) { d3 = d; i3 = i; }
            }
        }
        d3 = __shfl_sync(0xffffffffu, d3, L);
        i3 = __shfl_sync(0xffffffffu, i3, L);
        if (d3 < selD[2] || (d3 == selD[2] && i3 < selI[2])) {
            selD[2] = d3; selI[2] = i3;
        }
    }

    float d0 = fmaxf(selD[0] + q2, 1e-10f);
    float d1 = fmaxf(selD[1] + q2, 1e-10f);
    float d2 = fmaxf(selD[2] + q2, 1e-10f);
    float w0 = 1.f / (d0 + 1e-8f);
    float w1 = 1.f / (d1 + 1e-8f);
    float w2 = 1.f / (d2 + 1e-8f);
    float inv = 1.f / (w0 + w1 + w2);
    w0 *= inv; w1 *= inv; w2 *= inv;

    const float* p0f = pts1 + (size_t)(b * N1_ + selI[0]) * C1_;
    const float* p1f = pts1 + (size_t)(b * N1_ + selI[1]) * C1_;
    const float* p2f = pts1 + (size_t)(b * N1_ + selI[2]) * C1_;
    __half* xr = g_X + (size_t)row * INCH;

    const int c8 = lane * 8;
    {
        float4 a0 = *(const float4*)(p0f + c8);
        float4 b0 = *(const float4*)(p1f + c8);
        float4 c0 = *(const float4*)(p2f + c8);
        float4 a1 = *(const float4*)(p0f + c8 + 4);
        float4 b1 = *(const float4*)(p1f + c8 + 4);
        float4 c1 = *(const float4*)(p2f + c8 + 4);
        __half2 h[4];
        h[0] = __floats2half2_rn(w0*a0.x + w1*b0.x + w2*c0.x,
                                 w0*a0.y + w1*b0.y + w2*c0.y);
        h[1] = __floats2half2_rn(w0*a0.z + w1*b0.z + w2*c0.z,
                                 w0*a0.w + w1*b0.w + w2*c0.w);
        h[2] = __floats2half2_rn(w0*a1.x + w1*b1.x + w2*c1.x,
                                 w0*a1.y + w1*b1.y + w2*c1.y);
        h[3] = __floats2half2_rn(w0*a1.z + w1*b1.z + w2*c1.z,
                                 w0*a1.w + w1*b1.w + w2*c1.w);
        *(uint4*)(xr + c8) = *(uint4*)h;
    }
    {
        const float* pq = pts2 + (size_t)row * C2_;
        float4 v = *(const float4*)(pq + lane * 4);
        __half2 h[2];
        h[0] = __floats2half2_rn(v.x, v.y);
        h[1] = __floats2half2_rn(v.z, v.w);
        *(uint2*)(xr + C1_ + lane * 4) = *(uint2*)h;
    }
}

// ---------------------------------------------------------------------------
// Fused GEMM1+GEMM2 (frozen from R15): per CTA, 128 rows x ALL 256 cols.
//   Phase 1: Y1s[128x256] = relu(bn1(A[128x384] @ W1))   (Y1 stays in SMEM)
//   Phase 2: out[128x256] = relu(bn2(Y1s @ W2))          (A = SMEM ldmatrix)
// 512 threads = 16 warps (4m x 4n), warp 32x64. Race-free 4-stage pipeline.
// ---------------------------------------------------------------------------
__device__ __forceinline__ void cp16b(void* dst, const void* src) {
    uint32_t d = (uint32_t)__cvta_generic_to_shared(dst);
    asm volatile("cp.async.cg.shared.global [%0], [%1], 16;\n" :: "r"(d), "l"(src));
}
__device__ __forceinline__ void cp_commit() {
    asm volatile("cp.async.commit_group;\n");
}
__device__ __forceinline__ void cp_wait2() {
    asm volatile("cp.async.wait_group 2;\n");
}
__device__ __forceinline__ void cp_wait0() {
    asm volatile("cp.async.wait_group 0;\n");
}
__device__ __forceinline__ void ldsm_x4(uint32_t& r0, uint32_t& r1,
                                        uint32_t& r2, uint32_t& r3, uint32_t addr) {
    asm volatile("ldmatrix.sync.aligned.m8n8.x4.shared.b16 {%0,%1,%2,%3}, [%4];\n"
                 : "=r"(r0), "=r"(r1), "=r"(r2), "=r"(r3) : "r"(addr));
}
__device__ __forceinline__ void mma_f16(float c[4], const uint32_t a[4],
                                        uint32_t b0, uint32_t b1) {
    asm volatile(
        "mma.sync.aligned.m16n8k16.row.col.f32.f16.f16.f32 "
        "{%0,%1,%2,%3}, {%4,%5,%6,%7}, {%8,%9}, {%0,%1,%2,%3};"
        : "+f"(c[0]), "+f"(c[1]), "+f"(c[2]), "+f"(c[3])
        : "r"(a[0]), "r"(a[1]), "r"(a[2]), "r"(a[3]), "r"(b0), "r"(b1));
}

__global__ __launch_bounds__(512, 1) void gemm12_fused(
    const float* __restrict__ b1, const float* __restrict__ g1,
    const float* __restrict__ be1, const float* __restrict__ rm1,
    const float* __restrict__ rv1,
    const float* __restrict__ b2, const float* __restrict__ g2,
    const float* __restrict__ be2, const float* __restrict__ rm2,
    const float* __restrict__ rv2, float* __restrict__ out)
{
    extern __shared__ __align__(16) __half sm[];
    __half* y1s = sm + Y1OFF;

    const int tid  = threadIdx.x;
    const int lane = tid & 31;
    const int warp = tid >> 5;
    const int wm   = warp & 3;
    const int wn   = warp >> 2;
    const int m0   = blockIdx.x * 128;
    const int g4   = lane >> 2;
    const int c4   = lane & 3;

    const int a_r = tid >> 2, a_o = (tid & 3) * 8;
    const int w_r = tid >> 1, w_o = (tid & 1) * 16;

    const __half* Ag  = g_X   + (size_t)(m0 + a_r) * INCH + a_o;
    const __half* W1g = g_W1h + (size_t)w_r * INCH + w_o;
    const __half* W2g = g_W2h + (size_t)w_r * OUTCH + w_o;
    __half* sAme = sm + a_r * RSTR + a_o;
    __half* sWme = sm + APART + w_r * RSTR + w_o;

    const int a_row  = lane & 15;
    const int a_koff = (lane >= 16) ? 8 : 0;
    const int b_row  = ((lane >> 4) & 1) * 8 + (lane & 7);
    const int b_koff = ((lane >> 3) & 1) * 8;

    float acc[2][8][4];
    #pragma unroll
    for (int i = 0; i < 2; ++i)
        #pragma unroll
        for (int j = 0; j < 8; ++j)
            #pragma unroll
            for (int r = 0; r < 4; ++r) acc[i][j][r] = 0.f;

    // ================= Phase 1: A @ W1 =================
    constexpr int NK1 = INCH / BK;
    #pragma unroll
    for (int p = 0; p < STAGES - 1; ++p) {
        cp16b(sAme + p * STG, Ag + p * BK);
        cp16b(sWme + p * STG,     W1g + p * BK);
        cp16b(sWme + p * STG + 8, W1g + p * BK + 8);
        cp_commit();
    }

    for (int kt = 0; kt < NK1; ++kt) {
        cp_wait2();
        __syncthreads();

        const __half* stA = sm + (kt & (STAGES - 1)) * STG;
        const __half* stW = stA + APART;

        #pragma unroll
        for (int kk = 0; kk < 2; ++kk) {
            uint32_t fa[2][4], fb[8][2];
            #pragma unroll
            for (int i = 0; i < 2; ++i) {
                const int r = wm * 32 + i * 16 + a_row;
                uint32_t addr = (uint32_t)__cvta_generic_to_shared(
                    stA + r * RSTR + kk * 16 + a_koff);
                ldsm_x4(fa[i][0], fa[i][1], fa[i][2], fa[i][3], addr);
            }
            #pragma unroll
            for (int jh = 0; jh < 4; ++jh) {
                const int nr = wn * 64 + jh * 16 + b_row;
                uint32_t addr = (uint32_t)__cvta_generic_to_shared(
                    stW + nr * RSTR + kk * 16 + b_koff);
                ldsm_x4(fb[2*jh][0], fb[2*jh][1], fb[2*jh+1][0], fb[2*jh+1][1], addr);
            }
            #pragma unroll
            for (int i = 0; i < 2; ++i)
                #pragma unroll
                for (int j = 0; j < 8; ++j)
                    mma_f16(acc[i][j], fa[i], fb[j][0], fb[j][1]);
        }

        const int nxt = kt + STAGES - 1;
        if (nxt < NK1) {
            const int st = nxt & (STAGES - 1);
            cp16b(sAme + st * STG, Ag + nxt * BK);
            cp16b(sWme + st * STG,     W1g + nxt * BK);
            cp16b(sWme + st * STG + 8, W1g + nxt * BK + 8);
        }
        cp_commit();
    }

    // Phase-1 epilogue: bn1+relu -> half -> Y1 smem
    #pragma unroll
    for (int j = 0; j < 8; ++j) {
        const int c0 = wn * 64 + j * 8 + 2 * c4;
        const float s0 = g1[c0]   * rsqrtf(rv1[c0]   + 1e-5f);
        const float s1 = g1[c0+1] * rsqrtf(rv1[c0+1] + 1e-5f);
        const float h0 = (b1[c0]   - rm1[c0])   * s0 + be1[c0];
        const float h1 = (b1[c0+1] - rm1[c0+1]) * s1 + be1[c0+1];
        #pragma unroll
        for (int i = 0; i < 2; ++i) {
            const int r0 = wm * 32 + i * 16 + g4;
            __half2 lo = __floats2half2_rn(fmaxf(acc[i][j][0]*s0 + h0, 0.f),
                                           fmaxf(acc[i][j][1]*s1 + h1, 0.f));
            __half2 hi = __floats2half2_rn(fmaxf(acc[i][j][2]*s0 + h0, 0.f),
                                           fmaxf(acc[i][j][3]*s1 + h1, 0.f));
            *(__half2*)(y1s + r0 * RY + c0)       = lo;
            *(__half2*)(y1s + (r0 + 8) * RY + c0) = hi;
        }
    }

    cp_wait0();
    __syncthreads();

    // ================= Phase 2: Y1s @ W2 =================
    #pragma unroll
    for (int i = 0; i < 2; ++i)
        #pragma unroll
        for (int j = 0; j < 8; ++j)
            #pragma unroll
            for (int r = 0; r < 4; ++r) acc[i][j][r] = 0.f;

    constexpr int NK2 = OUTCH / BK;
    #pragma unroll
    for (int p = 0; p < STAGES - 1; ++p) {
        cp16b(sWme + p * STG,     W2g + p * BK);
        cp16b(sWme + p * STG + 8, W2g + p * BK + 8);
        cp_commit();
    }

    for (int kt = 0; kt < NK2; ++kt) {
        cp_wait2();
        __syncthreads();

        const __half* stW = sm + (kt & (STAGES - 1)) * STG + APART;

        #pragma unroll
        for (int kk = 0; kk < 2; ++kk) {
            uint32_t fa[2][4], fb[8][2];
            #pragma unroll
            for (int i = 0; i < 2; ++i) {
                const int r = wm * 32 + i * 16 + a_row;
                uint32_t addr = (uint32_t)__cvta_generic_to_shared(
                    y1s + r * RY + kt * 32 + kk * 16 + a_koff);
                ldsm_x4(fa[i][0], fa[i][1], fa[i][2], fa[i][3], addr);
            }
            #pragma unroll
            for (int jh = 0; jh < 4; ++jh) {
                const int nr = wn * 64 + jh * 16 + b_row;
                uint32_t addr = (uint32_t)__cvta_generic_to_shared(
                    stW + nr * RSTR + kk * 16 + b_koff);
                ldsm_x4(fb[2*jh][0], fb[2*jh][1], fb[2*jh+1][0], fb[2*jh+1][1], addr);
            }
            #pragma unroll
            for (int i = 0; i < 2; ++i)
                #pragma unroll
                for (int j = 0; j < 8; ++j)
                    mma_f16(acc[i][j], fa[i], fb[j][0], fb[j][1]);
        }

        const int nxt = kt + STAGES - 1;
        if (nxt < NK2) {
            const int st = nxt & (STAGES - 1);
            cp16b(sWme + st * STG,     W2g + nxt * BK);
            cp16b(sWme + st * STG + 8, W2g + nxt * BK + 8);
        }
        cp_commit();
    }

    // Phase-2 epilogue: bn2+relu -> fp32 gmem
    #pragma unroll
    for (int j = 0; j < 8; ++j) {
        const int c0 = wn * 64 + j * 8 + 2 * c4;
        const float s0 = g2[c0]   * rsqrtf(rv2[c0]   + 1e-5f);
        const float s1 = g2[c0+1] * rsqrtf(rv2[c0+1] + 1e-5f);
        const float h0 = (b2[c0]   - rm2[c0])   * s0 + be2[c0];
        const float h1 = (b2[c0+1] - rm2[c0+1]) * s1 + be2[c0+1];
        #pragma unroll
        for (int i = 0; i < 2; ++i) {
            const int r0 = m0 + wm * 32 + i * 16 + g4;
            float2 lo = make_float2(fmaxf(acc[i][j][0]*s0 + h0, 0.f),
                                    fmaxf(acc[i][j][1]*s1 + h1, 0.f));
            float2 hi = make_float2(fmaxf(acc[i][j][2]*s0 + h0, 0.f),
                                    fmaxf(acc[i][j][3]*s1 + h1, 0.f));
            *(float2*)(out + (size_t)r0 * OUTCH + c0)       = lo;
            *(float2*)(out + (size_t)(r0 + 8) * OUTCH + c0) = hi;
        }
    }
}

// ---------------------------------------------------------------------------
extern "C" void kernel_launch(void* const* d_in, const int* in_sizes, int n_in,
                              void* d_out, int out_size)
{
    const float* xyz1 = (const float*)d_in[0];
    const float* xyz2 = (const float*)d_in[1];
    const float* pts1 = (const float*)d_in[2];
    const float* pts2 = (const float*)d_in[3];
    const float* W1   = (const float*)d_in[4];
    const float* b1   = (const float*)d_in[5];
    const float* g1   = (const float*)d_in[6];
    const float* be1  = (const float*)d_in[7];
    const float* rm1  = (const float*)d_in[8];
    const float* rv1  = (const float*)d_in[9];
    const float* W2   = (const float*)d_in[10];
    const float* b2   = (const float*)d_in[11];
    const float* g2   = (const float*)d_in[12];
    const float* be2  = (const float*)d_in[13];
    const float* rm2  = (const float*)d_in[14];
    const float* rv2  = (const float*)d_in[15];
    float* out = (float*)d_out;

    static bool attr_set = false;
    if (!attr_set) {
        cudaFuncSetAttribute(gemm12_fused,
            cudaFuncAttributeMaxDynamicSharedMemorySize, DSMEM);
        attr_set = true;
    }

    prep_weights<<<dim3(INCH / 32, OUTCH / 32, 2), dim3(32, 8)>>>(W1, W2);
    knn_interp_kernel<<<dim3(N2_ / 16, B_), 512>>>(xyz1, xyz2, pts1, pts2);
    gemm12_fused<<<(B_ * N2_) / 128, 512, DSMEM>>>(
        b1, g1, be1, rm1, rv1, b2, g2, be2, rm2, rv2, out);
}